// round 1
// baseline (speedup 1.0000x reference)
#include <cuda_runtime.h>
#include <cstdint>

// Output: [1024, 201000] float32. Zero everything, then set 3 ones per row.

static constexpr int BATCH = 1024;
static constexpr int ENTITIES_N = 100000;
static constexpr int RELATIONS_N = 1000;
static constexpr long long WIDTH = (long long)ENTITIES_N * 2 + RELATIONS_N; // 201000
static constexpr long long TOTAL = (long long)BATCH * WIDTH;                // 205,824,000
static constexpr long long TOTAL4 = TOTAL / 4;                              // 51,456,000

__global__ void zero_fill_kernel(float4* __restrict__ out, long long n4) {
    long long i = (long long)blockIdx.x * blockDim.x + threadIdx.x;
    if (i < n4) {
        out[i] = make_float4(0.f, 0.f, 0.f, 0.f);
    }
}

__global__ void scatter_ones_kernel(float* __restrict__ out,
                                    const int* __restrict__ hID,
                                    const int* __restrict__ rID,
                                    const int* __restrict__ tID) {
    int row = blockIdx.x * blockDim.x + threadIdx.x;
    if (row < BATCH) {
        float* r = out + (long long)row * WIDTH;
        r[hID[row]] = 1.0f;
        r[ENTITIES_N + rID[row]] = 1.0f;
        r[ENTITIES_N + RELATIONS_N + tID[row]] = 1.0f;
    }
}

extern "C" void kernel_launch(void* const* d_in, const int* in_sizes, int n_in,
                              void* d_out, int out_size) {
    // inputs: z (float32, unused), hID (int32), rID (int32), tID (int32)
    const int* hID = (const int*)d_in[1];
    const int* rID = (const int*)d_in[2];
    const int* tID = (const int*)d_in[3];
    float* out = (float*)d_out;

    const int threads = 256;
    const long long blocks = (TOTAL4 + threads - 1) / threads;
    zero_fill_kernel<<<(unsigned)blocks, threads>>>((float4*)out, TOTAL4);
    scatter_ones_kernel<<<(BATCH + 255) / 256, 256>>>(out, hID, rID, tID);
}